// round 5
// baseline (speedup 1.0000x reference)
#include <cuda_runtime.h>
#include <cuda_fp16.h>
#include <cstdint>
#include <cstddef>

// ---------------- problem constants ----------------
static constexpr int S    = 2048;
static constexpr int DH   = 64;
static constexpr int DR   = 32;
static constexpr int TILE = 128;
static constexpr int KT   = S / TILE;          // 16 key tiles per pass
static constexpr float SCALE  = 0.125f;                 // 64^-0.5
static constexpr float RSCALE = 0.17677669529663689f;   // 32^-0.5
static constexpr float LOG2E  = 1.4426950408889634f;

// padded K-tile layout: 128 rows x 104 halfs (96 data + 8 pad), 208B row stride
static constexpr int ROWH       = 104;
static constexpr int TILE_HALFS = TILE * ROWH;          // 13312
static constexpr int TILE_BYTES = TILE_HALFS * 2;       // 26624
static constexpr int NTILES     = 64 * 16;

// scratch: pre-converted fp16 keys (rows permuted within 16-row groups for STG.128)
__device__ __align__(256) __half g_kh[(size_t)NTILES * TILE_HALFS];

// ---------------- smem layout ----------------
static constexpr int SM_STAT = 0;        // 6 x 128 floats
static constexpr int SM_B0   = 4096;
static constexpr int SM_B1   = SM_B0 + TILE_BYTES;
static constexpr int SMEM_TOTAL = SM_B1 + TILE_BYTES;   // 57344

// ---------------- PTX helpers ----------------
__device__ __forceinline__ uint32_t smem_u32(const void* p) {
    uint32_t a;
    asm("{ .reg .u64 t; cvta.to.shared.u64 t, %1; cvt.u32.u64 %0, t; }" : "=r"(a) : "l"(p));
    return a;
}
__device__ __forceinline__ float ex2f(float x) {
    float y; asm("ex2.approx.f32 %0, %1;" : "=f"(y) : "f"(x)); return y;
}
__device__ __forceinline__ void ldsm4(uint32_t* r, uint32_t addr) {
    asm volatile("ldmatrix.sync.aligned.m8n8.x4.shared.b16 {%0,%1,%2,%3}, [%4];"
                 : "=r"(r[0]), "=r"(r[1]), "=r"(r[2]), "=r"(r[3]) : "r"(addr));
}
__device__ __forceinline__ void mma16816(float* c, const uint32_t* a, const uint32_t* b) {
    asm volatile(
        "mma.sync.aligned.m16n8k16.row.col.f32.f16.f16.f32 "
        "{%0,%1,%2,%3}, {%4,%5,%6,%7}, {%8,%9}, {%0,%1,%2,%3};"
        : "+f"(c[0]), "+f"(c[1]), "+f"(c[2]), "+f"(c[3])
        : "r"(a[0]), "r"(a[1]), "r"(a[2]), "r"(a[3]), "r"(b[0]), "r"(b[1]));
}
__device__ __forceinline__ void cpa16(uint32_t daddr, const void* src) {
    asm volatile("cp.async.cg.shared.global [%0], [%1], 16;" :: "r"(daddr), "l"(src) : "memory");
}
#define CP_COMMIT() asm volatile("cp.async.commit_group;" ::: "memory")
#define CP_WAIT1()  asm volatile("cp.async.wait_group 1;" ::: "memory")
#define CP_WAIT0()  asm volatile("cp.async.wait_group 0;" ::: "memory")

// ---------------- pre-conversion kernel (K side only) ----------------
// Row permutation within 16-row groups so pass-2 can use STG.128:
//   logical key s -> physical row p = (s & ~15) | ((s>>1)&1)<<3 | ((s>>2)&3)<<1 | (s&1)
__global__ void __launch_bounds__(384) convert_kernel(
    const float* __restrict__ keys, const float* __restrict__ pos_key) {
    const int rg = blockIdx.x * 4 + threadIdx.x / 96;   // bh*2048 + s
    const int j  = threadIdx.x % 96;
    const size_t tile = (size_t)(rg >> 7);
    const int s = rg & 127;
    const int p = (s & ~15) | (((s >> 1) & 1) << 3) | (((s >> 2) & 3) << 1) | (s & 1);
    const size_t off = tile * TILE_HALFS + (size_t)p * ROWH + j;

    float v = (j < DH) ? keys[(size_t)rg * DH + j]
                       : pos_key[(size_t)rg * DR + (j - DH)];
    g_kh[off] = __float2half_rn(fminf(fmaxf(v, -5.0f), 5.0f));
}

// ---------------- main attention-map kernel ----------------
__device__ __forceinline__ void copy_tile(uint32_t dsm, const __half* src, int tid) {
    const char* s = reinterpret_cast<const char*>(src);
#pragma unroll
    for (int i = tid * 16; i < TILE_BYTES; i += 256 * 16)
        cpa16(dsm + i, s + i);
}

// Load one 4-byte A-fragment reg (2 halfs) directly from fp32 gmem with clamp+scale.
// col is a compile-time-resolved constant per unrolled ks.
__device__ __forceinline__ uint32_t ldq_pair(const float* __restrict__ q,
                                             const float* __restrict__ pq,
                                             int row, int col) {
    float2 v;
    float scl;
    if (col < DH) {
        v = *reinterpret_cast<const float2*>(q + (size_t)row * DH + col);
        scl = SCALE * LOG2E;
    } else {
        v = *reinterpret_cast<const float2*>(pq + (size_t)row * DR + (col - DH));
        scl = RSCALE * LOG2E;
    }
    __half2 h = __floats2half2_rn(fminf(fmaxf(v.x, -5.0f), 5.0f) * scl,
                                  fminf(fmaxf(v.y, -5.0f), 5.0f) * scl);
    return *reinterpret_cast<uint32_t*>(&h);
}

__global__ void __launch_bounds__(256, 2)
attnmap_kernel(const float* __restrict__ queries,
               const float* __restrict__ pos_query,
               float* __restrict__ out) {
    extern __shared__ char smem[];
    const int tid  = threadIdx.x;
    const int wid  = tid >> 5, lane = tid & 31;
    const int qt   = blockIdx.x;
    const int bh   = blockIdx.y;
    const uint32_t sb = smem_u32(smem);

    const int warpM = (wid >> 1) << 5;   // 0,32,64,96
    const int warpN = (wid & 1) << 6;    // 0,64

    // ---- A fragments: load once from gmem, keep in registers for all 32 tiles ----
    const float* qbase = queries   + (size_t)(bh * S + qt * TILE) * DH;
    const float* pbase = pos_query + (size_t)(bh * S + qt * TILE) * DR;
    uint32_t afrag[2][6][4];
#pragma unroll
    for (int mi = 0; mi < 2; mi++) {
        const int r0 = warpM + mi * 16 + (lane >> 2);
        const int r1 = r0 + 8;
#pragma unroll
        for (int ks = 0; ks < 6; ks++) {
            const int c0 = ks * 16 + (lane & 3) * 2;
            afrag[mi][ks][0] = ldq_pair(qbase, pbase, r0, c0);
            afrag[mi][ks][1] = ldq_pair(qbase, pbase, r1, c0);
            afrag[mi][ks][2] = ldq_pair(qbase, pbase, r0, c0 + 8);
            afrag[mi][ks][3] = ldq_pair(qbase, pbase, r1, c0 + 8);
        }
    }

    // per-lane ldmatrix base byte-offsets for B
    uint32_t bbase[4];
#pragma unroll
    for (int nq = 0; nq < 4; nq++) {
        int row = warpN + nq * 16 + (lane & 7) + (((lane >> 4) & 1) << 3);
        bbase[nq] = (uint32_t)(row * 208 + (((lane >> 3) & 1) << 4));
    }

    const __half* khb = g_kh + (size_t)(bh * 16) * TILE_HALFS;

    // prologue: key-tile 0
    copy_tile(sb + SM_B0, khb, tid);
    CP_COMMIT();

    float* st_m0 = reinterpret_cast<float*>(smem + SM_STAT);
    float* st_l0 = st_m0 + 128;
    float* st_m1 = st_m0 + 256;
    float* st_l1 = st_m0 + 384;
    float* st_M  = st_m0 + 512;
    float* st_I  = st_m0 + 640;

    float m2[4], l2[4], Ms[4] = {0, 0, 0, 0}, Is[4] = {0, 0, 0, 0};
#pragma unroll
    for (int sl = 0; sl < 4; sl++) { m2[sl] = -1e30f; l2[sl] = 0.0f; }

    for (int gt = 0; gt < 2 * KT; gt++) {
        const int kt = gt & 15;
        __syncthreads();    // prior compute done before overwriting prefetch buffer
        if (gt + 1 < 2 * KT) {
            const int ktn = (gt + 1) & 15;
            copy_tile(sb + (((gt + 1) & 1) ? SM_B1 : SM_B0),
                      khb + (size_t)ktn * TILE_HALFS, tid);
            CP_COMMIT();
            CP_WAIT1();
        } else {
            CP_WAIT0();
        }
        __syncthreads();    // current tile visible to all warps

        const uint32_t sB = sb + ((gt & 1) ? SM_B1 : SM_B0);

        float c[2][8][4];
#pragma unroll
        for (int mi = 0; mi < 2; mi++)
#pragma unroll
            for (int ni = 0; ni < 8; ni++)
#pragma unroll
                for (int j = 0; j < 4; j++) c[mi][ni][j] = 0.0f;

#pragma unroll
        for (int ks = 0; ks < 6; ks++) {
            const uint32_t ko = (uint32_t)(ks * 32);
#pragma unroll
            for (int nq = 0; nq < 4; nq++) {
                uint32_t b4[4];
                ldsm4(b4, sB + bbase[nq] + ko);
#pragma unroll
                for (int mi = 0; mi < 2; mi++) {
#pragma unroll
                    for (int nb = 0; nb < 2; nb++) {
                        const int ni = nq * 2 + nb;
                        mma16816(c[mi][ni], afrag[mi][ks], &b4[nb * 2]);
                    }
                }
            }
        }

        if (gt < KT) {
            // ---- pass 1: online row stats (scores in log2 domain; perm-invariant) ----
#pragma unroll
            for (int mi = 0; mi < 2; mi++) {
#pragma unroll
                for (int rh = 0; rh < 2; rh++) {
                    const int sl = mi * 2 + rh;
                    float cm = -1e30f;
#pragma unroll
                    for (int ni = 0; ni < 8; ni++)
                        cm = fmaxf(cm, fmaxf(c[mi][ni][rh * 2], c[mi][ni][rh * 2 + 1]));
                    const float mn = fmaxf(m2[sl], cm);
                    const float corr = ex2f(m2[sl] - mn);
                    float acc = 0.0f;
#pragma unroll
                    for (int ni = 0; ni < 8; ni++)
                        acc += ex2f(c[mi][ni][rh * 2] - mn) + ex2f(c[mi][ni][rh * 2 + 1] - mn);
                    l2[sl] = l2[sl] * corr + acc;
                    m2[sl] = mn;
                }
            }
            if (gt == KT - 1) {
#pragma unroll
                for (int d = 1; d <= 2; d <<= 1) {
#pragma unroll
                    for (int sl = 0; sl < 4; sl++) {
                        const float mo = __shfl_xor_sync(0xFFFFFFFFu, m2[sl], d);
                        const float lo = __shfl_xor_sync(0xFFFFFFFFu, l2[sl], d);
                        const float mn = fmaxf(m2[sl], mo);
                        l2[sl] = l2[sl] * ex2f(m2[sl] - mn) + lo * ex2f(mo - mn);
                        m2[sl] = mn;
                    }
                }
                if ((lane & 3) == 0) {
#pragma unroll
                    for (int sl = 0; sl < 4; sl++) {
                        const int row = warpM + (sl >> 1) * 16 + (sl & 1) * 8 + (lane >> 2);
                        if ((wid & 1) == 0) { st_m0[row] = m2[sl]; st_l0[row] = l2[sl]; }
                        else                { st_m1[row] = m2[sl]; st_l1[row] = l2[sl]; }
                    }
                }
                __syncthreads();
                if (tid < 128) {
                    const float ma = st_m0[tid], mb = st_m1[tid];
                    const float Mx = fmaxf(ma, mb);
                    const float L = st_l0[tid] * ex2f(ma - Mx) + st_l1[tid] * ex2f(mb - Mx);
                    st_M[tid] = Mx;
                    st_I[tid] = 1.0f / L;
                }
                __syncthreads();
#pragma unroll
                for (int sl = 0; sl < 4; sl++) {
                    const int row = warpM + (sl >> 1) * 16 + (sl & 1) * 8 + (lane >> 2);
                    Ms[sl] = st_M[row];
                    Is[sl] = st_I[row];
                }
            }
        } else {
            // ---- pass 2: normalize + STG.128 (key permutation makes cols contiguous) ----
#pragma unroll
            for (int mi = 0; mi < 2; mi++) {
                const int rbase = qt * TILE + warpM + mi * 16 + (lane >> 2);
                const float M0 = Ms[mi * 2], I0 = Is[mi * 2];
                const float M1 = Ms[mi * 2 + 1], I1 = Is[mi * 2 + 1];
                float* o0 = out + ((size_t)(bh * S + rbase) * S)
                          + (size_t)(kt * TILE + warpN) + ((lane & 3) << 2);
                float* o1 = o0 + 8 * (size_t)S;
#pragma unroll
                for (int g = 0; g < 4; g++) {
                    float4 v0, v1;
                    v0.x = ex2f(c[mi][2 * g][0] - M0) * I0;
                    v0.y = ex2f(c[mi][2 * g][1] - M0) * I0;
                    v0.z = ex2f(c[mi][2 * g + 1][0] - M0) * I0;
                    v0.w = ex2f(c[mi][2 * g + 1][1] - M0) * I0;
                    v1.x = ex2f(c[mi][2 * g][2] - M1) * I1;
                    v1.y = ex2f(c[mi][2 * g][3] - M1) * I1;
                    v1.z = ex2f(c[mi][2 * g + 1][2] - M1) * I1;
                    v1.w = ex2f(c[mi][2 * g + 1][3] - M1) * I1;
                    reinterpret_cast<float4*>(o0)[g * 4] = v0;   // g*16 floats
                    reinterpret_cast<float4*>(o1)[g * 4] = v1;
                }
            }
        }
    }
}

// ---------------- launch ----------------
extern "C" void kernel_launch(void* const* d_in, const int* in_sizes, int n_in,
                              void* d_out, int out_size) {
    (void)in_sizes; (void)n_in; (void)out_size;
    const float* keys      = (const float*)d_in[0];
    const float* queries   = (const float*)d_in[1];
    const float* pos_key   = (const float*)d_in[2];
    const float* pos_query = (const float*)d_in[3];
    float* out = (float*)d_out;

    convert_kernel<<<64 * S / 4, 384>>>(keys, pos_key);

    cudaFuncSetAttribute(attnmap_kernel, cudaFuncAttributeMaxDynamicSharedMemorySize, SMEM_TOTAL);
    dim3 grid(S / TILE, 64, 1);
    attnmap_kernel<<<grid, 256, SMEM_TOTAL>>>(queries, pos_query, out);
}